// round 3
// baseline (speedup 1.0000x reference)
#include <cuda_runtime.h>
#include <math.h>

#define Bsz   4
#define Lsz   4096
#define Esz   1024
#define Hsz   16
#define Dsz   64
#define HEADS 64
#define SPLIT 18
#define CHUNK 232            // max tokens per split (multiple of GT; last split = 152)
#define GT    8              // tokens staged per group (phase 1)

#define PART   8320          // A(4096) + B(4096) + ks(64) + kc(64)
#define OFF_A  0
#define OFF_B  4096
#define OFF_KS 8192
#define OFF_KC 8256

// Scratch (no allocations allowed in kernel_launch)
__device__ float g_part[HEADS * SPLIT * PART];   // ~38 MB
__device__ float g_kv[HEADS * PART];             // ~2.1 MB

// ---------------------------------------------------------------------------
// Phase 1: per (head, L-split) partial accumulation.
//   threads 0..63  : A[d][m] += s_l*relu(k)[d] * (mask^2 folded) * v[m], 8x8 tile
//   threads 64..127: B[d][m] with cos
// Register-prefetch double buffering: LDG for group g+1 issued before the
// compute of group g, so global latency overlaps the FMA stream.
// ---------------------------------------------------------------------------
__global__ __launch_bounds__(128) void k_phase1(const float* __restrict__ K,
                                                const float* __restrict__ V,
                                                const float* __restrict__ M) {
    int blk = blockIdx.x;
    int n  = blk / SPLIT;
    int sp = blk - n * SPLIT;
    int b = n >> 4, h = n & 15;
    int l0 = sp * CHUNK;
    int cnt = Lsz - l0; if (cnt > CHUNK) cnt = CHUNK;   // 232 or 152

    const float* kb = K + ((size_t)b * Lsz + l0) * Esz + h * Dsz;
    const float* vb = V + ((size_t)b * Lsz + l0) * Esz + h * Dsz;
    const float* mb = M + (size_t)b * Lsz + l0;

    __shared__ float ssh[CHUNK], csh[CHUNK], msh[CHUNK];
    __shared__ float skh[GT * 64];   // s_l * mask * relu(k)
    __shared__ float ckh[GT * 64];   // c_l * mask * relu(k)
    __shared__ float vmh[GT * 64];   // mask * v

    int t = threadIdx.x;

    // per-token sin/cos (mask folded) for the whole chunk
    for (int i = t; i < cnt; i += 128) {
        int l = l0 + i;
        float ang = 1.5707963267948966f * (float)(l + 1) / (float)Lsz;
        float m = mb[i];
        ssh[i] = sinf(ang) * m;
        csh[i] = cosf(ang) * m;
        msh[i] = m;
    }
    __syncthreads();

    bool isA = (t < 64);
    int tt = t & 63;
    int dg = tt >> 3;          // d block: d = dg*8 .. dg*8+7
    int mg = tt & 7;           // m block: m = mg*8 .. mg*8+7
    const float* xsh = isA ? skh : ckh;

    // staging slot: GT*64 = 512 floats = 128 float4 -> one float4 of k and v each
    int tok = t >> 4;
    int dd  = (t & 15) * 4;

    float acc[8][8];
    #pragma unroll
    for (int i = 0; i < 8; ++i)
        #pragma unroll
        for (int j = 0; j < 8; ++j) acc[i][j] = 0.f;
    float aks = 0.f;           // ks[tt] for A-threads, kc[tt] for B-threads

    int ng = cnt / GT;

    // prefetch group 0
    float4 pk = *(const float4*)&kb[(size_t)tok * Esz + dd];
    float4 pv = *(const float4*)&vb[(size_t)tok * Esz + dd];

    for (int g = 0; g < ng; ++g) {
        // store staged group (feature-map math folded here, once per element)
        {
            int li = g * GT + tok;
            float s = ssh[li], c = csh[li], m = msh[li];
            float rx = fmaxf(pk.x, 0.f), ry = fmaxf(pk.y, 0.f);
            float rz = fmaxf(pk.z, 0.f), rw = fmaxf(pk.w, 0.f);
            *(float4*)&skh[tok * 64 + dd] = make_float4(rx * s, ry * s, rz * s, rw * s);
            *(float4*)&ckh[tok * 64 + dd] = make_float4(rx * c, ry * c, rz * c, rw * c);
            *(float4*)&vmh[tok * 64 + dd] = make_float4(pv.x * m, pv.y * m, pv.z * m, pv.w * m);
        }
        __syncthreads();

        // prefetch next group (latency overlapped with compute below)
        if (g + 1 < ng) {
            size_t o = (size_t)((g + 1) * GT + tok) * Esz + dd;
            pk = *(const float4*)&kb[o];
            pv = *(const float4*)&vb[o];
        }

        // ks/kc column sums (each thread owns one d = tt)
        #pragma unroll
        for (int k = 0; k < GT; ++k) aks += xsh[k * 64 + tt];

        // 8x8 outer-product accumulation
        #pragma unroll
        for (int k = 0; k < GT; ++k) {
            float x[8], y[8];
            float4 x0 = *(const float4*)&xsh[k * 64 + dg * 8];
            float4 x1 = *(const float4*)&xsh[k * 64 + dg * 8 + 4];
            float4 y0 = *(const float4*)&vmh[k * 64 + mg * 8];
            float4 y1 = *(const float4*)&vmh[k * 64 + mg * 8 + 4];
            x[0]=x0.x; x[1]=x0.y; x[2]=x0.z; x[3]=x0.w;
            x[4]=x1.x; x[5]=x1.y; x[6]=x1.z; x[7]=x1.w;
            y[0]=y0.x; y[1]=y0.y; y[2]=y0.z; y[3]=y0.w;
            y[4]=y1.x; y[5]=y1.y; y[6]=y1.z; y[7]=y1.w;
            #pragma unroll
            for (int i = 0; i < 8; ++i)
                #pragma unroll
                for (int j = 0; j < 8; ++j)
                    acc[i][j] += x[i] * y[j];
        }
        __syncthreads();
    }

    float* p = g_part + (size_t)blk * PART;
    int off = isA ? OFF_A : OFF_B;
    #pragma unroll
    for (int i = 0; i < 8; ++i) {
        int d = dg * 8 + i;
        *(float4*)&p[off + d * 64 + mg * 8] =
            make_float4(acc[i][0], acc[i][1], acc[i][2], acc[i][3]);
        *(float4*)&p[off + d * 64 + mg * 8 + 4] =
            make_float4(acc[i][4], acc[i][5], acc[i][6], acc[i][7]);
    }
    p[(isA ? OFF_KS : OFF_KC) + tt] = aks;
}

// ---------------------------------------------------------------------------
// Reduce the SPLIT partials per head (deterministic, fixed order)
// 512 blocks: 8 slices of 1040 elements per head.
// ---------------------------------------------------------------------------
__global__ __launch_bounds__(256) void k_reduce() {
    int blk = blockIdx.x;
    int n = blk >> 3;
    int sl = blk & 7;
    int base = sl * 1040;
    for (int i = base + threadIdx.x; i < base + 1040; i += 256) {
        float s = 0.f;
        #pragma unroll
        for (int sp = 0; sp < SPLIT; ++sp)
            s += g_part[(size_t)(n * SPLIT + sp) * PART + i];
        g_kv[(size_t)n * PART + i] = s;
    }
}

// ---------------------------------------------------------------------------
// Phase 2: out[l][m] = z_l * ( rqs[l]@A + rqc[l]@B )[m]
//   rqs = s_l*relu(q), rqc = c_l*relu(q) folded at staging time.
// Tile: 128 tokens x 64 m per block, thread tile 8 tok x 8 m.
// ---------------------------------------------------------------------------
#define TT    128
#define RQS   65
#define SM2_FLOATS (4096 + 4096 + 2 * TT * RQS + 3 * TT + 128)
#define SM2_BYTES  (SM2_FLOATS * 4)

__global__ __launch_bounds__(128) void k_phase2(const float* __restrict__ Q,
                                                float* __restrict__ O) {
    extern __shared__ float sm2[];
    float* Ash  = sm2;
    float* Bsh  = sm2 + 4096;
    float* rqs  = sm2 + 8192;
    float* rqc  = rqs + TT * RQS;
    float* ssh  = rqc + TT * RQS;
    float* csh  = ssh + TT;
    float* zsh  = csh + TT;
    float* ks2  = zsh + TT;
    float* kc2  = ks2 + 64;

    int blk = blockIdx.x;
    int n = blk >> 5;          // head
    int tile = blk & 31;       // 128-token tile
    int b = n >> 4, h = n & 15;
    int l0 = tile * TT;

    const float* qb = Q + ((size_t)b * Lsz + l0) * Esz + h * Dsz;
    const float* kv = g_kv + (size_t)n * PART;
    int t = threadIdx.x;

    // stage A, B, ks, kc, per-token sin/cos
    #pragma unroll
    for (int j = 0; j < 8; ++j) {
        int e4 = j * 128 + t;
        *(float4*)&Ash[e4 * 4] = *(const float4*)&kv[OFF_A + e4 * 4];
        *(float4*)&Bsh[e4 * 4] = *(const float4*)&kv[OFF_B + e4 * 4];
    }
    if (t < 64) {
        ks2[t] = kv[OFF_KS + t];
        kc2[t] = kv[OFF_KC + t];
    }
    {
        int l = l0 + t;
        float ang = 1.5707963267948966f * (float)(l + 1) / (float)Lsz;
        ssh[t] = sinf(ang);
        csh[t] = cosf(ang);
    }
    __syncthreads();

    // stage s*relu(q), c*relu(q): [tok][d], row stride 65 (conflict-free cols)
    #pragma unroll
    for (int j = 0; j < 16; ++j) {
        int e4 = j * 128 + t;
        int tok = e4 >> 4;
        int dd = (e4 & 15) * 4;
        float s = ssh[tok], c = csh[tok];
        float4 q4 = *(const float4*)&qb[(size_t)tok * Esz + dd];
        float rx = fmaxf(q4.x, 0.f), ry = fmaxf(q4.y, 0.f);
        float rz = fmaxf(q4.z, 0.f), rw = fmaxf(q4.w, 0.f);
        float* rs = &rqs[tok * RQS + dd];
        float* rc = &rqc[tok * RQS + dd];
        rs[0] = rx * s; rs[1] = ry * s; rs[2] = rz * s; rs[3] = rw * s;
        rc[0] = rx * c; rc[1] = ry * c; rc[2] = rz * c; rc[3] = rw * c;
    }
    __syncthreads();

    // normalizer: one token per thread
    {
        float a = 0.f;
        const float* rs = &rqs[t * RQS];
        const float* rc = &rqc[t * RQS];
        #pragma unroll 8
        for (int d = 0; d < 64; ++d)
            a += rs[d] * ks2[d] + rc[d] * kc2[d];
        zsh[t] = 1.f / fmaxf(a, 1e-6f);
    }
    __syncthreads();

    int tg = t >> 3;           // token group (0..15): tokens tg*8..tg*8+7
    int mg = t & 7;            // m group: m = mg*8..mg*8+7
    int m0 = mg * 8;

    float acc[8][8];
    #pragma unroll
    for (int i = 0; i < 8; ++i)
        #pragma unroll
        for (int j = 0; j < 8; ++j) acc[i][j] = 0.f;

    #pragma unroll 4
    for (int d = 0; d < 64; ++d) {
        float ra[8], rb[8];
        #pragma unroll
        for (int i = 0; i < 8; ++i) {
            ra[i] = rqs[(tg * 8 + i) * RQS + d];
            rb[i] = rqc[(tg * 8 + i) * RQS + d];
        }
        float4 a0 = *(const float4*)&Ash[d * 64 + m0];
        float4 a1 = *(const float4*)&Ash[d * 64 + m0 + 4];
        float4 b0 = *(const float4*)&Bsh[d * 64 + m0];
        float4 b1 = *(const float4*)&Bsh[d * 64 + m0 + 4];
        float aa[8] = { a0.x, a0.y, a0.z, a0.w, a1.x, a1.y, a1.z, a1.w };
        float bb[8] = { b0.x, b0.y, b0.z, b0.w, b1.x, b1.y, b1.z, b1.w };
        #pragma unroll
        for (int i = 0; i < 8; ++i)
            #pragma unroll
            for (int j = 0; j < 8; ++j)
                acc[i][j] += ra[i] * aa[j] + rb[i] * bb[j];
    }

    float* ob = O + ((size_t)n * Lsz + l0) * Dsz;
    #pragma unroll
    for (int i = 0; i < 8; ++i) {
        int tok = tg * 8 + i;
        float z = zsh[tok];
        *(float4*)&ob[(size_t)tok * Dsz + m0] =
            make_float4(acc[i][0] * z, acc[i][1] * z, acc[i][2] * z, acc[i][3] * z);
        *(float4*)&ob[(size_t)tok * Dsz + m0 + 4] =
            make_float4(acc[i][4] * z, acc[i][5] * z, acc[i][6] * z, acc[i][7] * z);
    }
}

// ---------------------------------------------------------------------------
extern "C" void kernel_launch(void* const* d_in, const int* in_sizes, int n_in,
                              void* d_out, int out_size) {
    const float* q = (const float*)d_in[0];
    const float* k = (const float*)d_in[1];
    const float* v = (const float*)d_in[2];
    const float* m = (const float*)d_in[3];
    float* out = (float*)d_out;

    cudaFuncSetAttribute(k_phase2, cudaFuncAttributeMaxDynamicSharedMemorySize,
                         SM2_BYTES);

    k_phase1<<<HEADS * SPLIT, 128>>>(k, v, m);
    k_reduce<<<HEADS * 8, 256>>>();
    k_phase2<<<HEADS * 32, 128, SM2_BYTES>>>(q, out);
}